// round 14
// baseline (speedup 1.0000x reference)
#include <cuda_runtime.h>
#include <cuda_fp16.h>
#include <cstdint>
#include <math.h>

#define BATCH 16
#define NNODE 512
#define IDIM  512
#define HDIM  1024

#define RNB 296          // persistent blocks, occupancy 2
#define RNT 256
#define NKC 16           // wide path: 16 k-chunks of 64 halves
#define STAGE_BYTES 20480

// SMEM layout (bytes)
#define SM_LOFF 0            // 516 ints
#define SM_VS   2064         // 24 rows x 2064 B = 49536 (V slice, fp16)
#define VS_ROWH 1032         // row stride in halves
#define SM_STG  51600        // 3 x 20480 = 61440
#define SM_META 113040       // 192 ints
#define SMEM_TOTAL 113808

// ---------------- device scratch ----------------
__device__ __half g_Vh[3u * HDIM * HDIM];         // V_g fp16 [g][n][k] (symmetric)
__device__ __half g_hph[BATCH * NNODE * HDIM];    // fp16 mirror of tree_h
__device__ float  g_inp0f[BATCH * HDIM];
__device__ float  g_inp0o[BATCH * HDIM];
__device__ float  g_inp0z[BATCH * HDIM];
__device__ float  g_tree_c[BATCH * NNODE * HDIM];
__device__ int    g_meta[BATCH * NNODE];          // prow | irow<<13 (13-bit rows)
__device__ int    g_level_off[NNODE + 1];
__device__ int    g_num_levels;
__device__ unsigned int g_bar;

// ---------------- helpers ----------------
__device__ __forceinline__ void mma_tf32(float* d, const uint32_t* a, const uint32_t* b) {
    asm volatile(
        "mma.sync.aligned.m16n8k8.row.col.f32.tf32.tf32.f32 "
        "{%0,%1,%2,%3}, {%4,%5,%6,%7}, {%8,%9}, {%0,%1,%2,%3};\n"
        : "+f"(d[0]), "+f"(d[1]), "+f"(d[2]), "+f"(d[3])
        : "r"(a[0]), "r"(a[1]), "r"(a[2]), "r"(a[3]), "r"(b[0]), "r"(b[1]));
}
__device__ __forceinline__ void mma_f16(float* d, const uint32_t* a, const uint32_t* b) {
    asm volatile(
        "mma.sync.aligned.m16n8k16.row.col.f32.f16.f16.f32 "
        "{%0,%1,%2,%3}, {%4,%5,%6,%7}, {%8,%9}, {%0,%1,%2,%3};\n"
        : "+f"(d[0]), "+f"(d[1]), "+f"(d[2]), "+f"(d[3])
        : "r"(a[0]), "r"(a[1]), "r"(a[2]), "r"(a[3]), "r"(b[0]), "r"(b[1]));
}
__device__ __forceinline__ void ldsm_x4(uint32_t* r, uint32_t addr) {
    asm volatile("ldmatrix.sync.aligned.m8n8.x4.shared.b16 {%0,%1,%2,%3}, [%4];"
        : "=r"(r[0]), "=r"(r[1]), "=r"(r[2]), "=r"(r[3]) : "r"(addr));
}
#define CP_ASYNC16(dst_u32, src_ptr) \
    asm volatile("cp.async.cg.shared.global [%0], [%1], 16;" :: "r"(dst_u32), "l"(src_ptr))
#define CP_COMMIT() asm volatile("cp.async.commit_group;" ::: "memory")
#define CP_WAIT(n)  asm volatile("cp.async.wait_group %0;" :: "n"(n) : "memory")

__device__ __forceinline__ float sigf(float x) {
    return __fdividef(1.0f, 1.0f + __expf(-x));
}
__device__ __forceinline__ float tanf_(float x) {
    return 1.0f - __fdividef(2.0f, 1.0f + __expf(2.0f * x));
}

// ---------------- setup: reset + levels + counting sort + packed meta ----------
__global__ void setup_kernel(const int* __restrict__ conn) {
    __shared__ unsigned short lvl[BATCH][NNODE];
    __shared__ int counts[NNODE];
    __shared__ int offs[NNODE + 1];
    __shared__ int cur[NNODE];
    int tid = threadIdx.x;
    if (tid == 0) g_bar = 0u;
    for (int l = tid; l < NNODE; l += blockDim.x) counts[l] = 0;
    __syncthreads();
    if (tid < BATCH) {
        int b = tid;
        lvl[b][0] = 0;
        for (int i = 1; i < NNODE; i++) {
            int p = conn[b * NNODE + i];
            lvl[b][i] = (unsigned short)(lvl[b][p] + 1);
        }
    }
    __syncthreads();
    for (int t = tid; t < BATCH * NNODE; t += blockDim.x) {
        int i = t & (NNODE - 1);
        if (i != 0) atomicAdd(&counts[lvl[t >> 9][i]], 1);
    }
    __syncthreads();
    if (tid == 0) {
        int acc = 0, maxl = 0;
        for (int l = 0; l < NNODE; l++) {
            offs[l] = acc;
            acc += counts[l];
            if (counts[l] > 0) maxl = l;
        }
        offs[NNODE] = acc;
        g_num_levels = maxl + 1;
    }
    __syncthreads();
    for (int l = tid; l <= NNODE; l += blockDim.x) g_level_off[l] = offs[l];
    for (int l = tid; l < NNODE; l += blockDim.x) cur[l] = offs[l];
    __syncthreads();
    for (int t = tid; t < BATCH * NNODE; t += blockDim.x) {
        int b = t >> 9, i = t & (NNODE - 1);
        if (i != 0) {
            int p = conn[b * NNODE + i];
            int pos = atomicAdd(&cur[lvl[b][i]], 1);
            g_meta[pos] = ((b << 9) + p) | (((b << 9) + i) << 13);
        }
    }
}

// ---------------- inp0 (only node 0 matters) + roots ----------------
__global__ void inp0_kernel(const float* __restrict__ emb,
                            const float* __restrict__ Wf, const float* __restrict__ bf,
                            const float* __restrict__ Wo, const float* __restrict__ bo,
                            const float* __restrict__ Wz, const float* __restrict__ bz,
                            float* __restrict__ tree_h) {
    int t = blockIdx.x * blockDim.x + threadIdx.x;
    int b = t >> 10, n = t & (HDIM - 1);
    const float* x = emb + (size_t)b * NNODE * IDIM;
    float af = bf[n], ao = bo[n], az = bz[n];
#pragma unroll 8
    for (int k = 0; k < IDIM; k++) {
        float xv = __ldg(&x[k]);
        af = fmaf(xv, Wf[k * HDIM + n], af);
        ao = fmaf(xv, Wo[k * HDIM + n], ao);
        az = fmaf(xv, Wz[k * HDIM + n], az);
    }
    g_inp0f[t] = af; g_inp0o[t] = ao; g_inp0z[t] = az;
    float f = 1.0f / (1.0f + expf(-af));
    float o = 1.0f / (1.0f + expf(-ao));
    float z = tanhf(az);
    float c = z * (1.0f - f);
    float h = o * tanhf(c);
    int row = (b * NNODE) << 10;
    tree_h[row + n] = h;
    g_hph[row + n] = __float2half(h);
    g_tree_c[row + n] = c;
}

// ---------------- V = T^T T, upper-triangular tiles + mirror ----------------
#define NTRI 136
__global__ void v_kernel(const float* __restrict__ Tf,
                         const float* __restrict__ To,
                         const float* __restrict__ Tz) {
    __shared__ float Ats[32][68];
    __shared__ float Bts[32][68];
    int bid = blockIdx.x;
    int g = bid / NTRI;
    int t = bid - g * NTRI;
    int ti = 0;
    while (t >= 16 - ti) { t -= 16 - ti; ti++; }
    int tj = ti + t;
    int m0 = ti << 6, n0 = tj << 6;
    const float* T = (g == 0) ? Tf : (g == 1) ? To : Tz;
    int tid = threadIdx.x, lane = tid & 31, wid = tid >> 5;
    int moff = (wid >> 2) << 5, noff = (wid & 3) << 4;

    float acc[2][2][4];
#pragma unroll
    for (int mf = 0; mf < 2; mf++)
#pragma unroll
        for (int nf = 0; nf < 2; nf++)
#pragma unroll
            for (int j = 0; j < 4; j++) acc[mf][nf][j] = 0.0f;

    for (int k0 = 0; k0 < HDIM; k0 += 32) {
#pragma unroll
        for (int q = 0; q < 2; q++) {
            int fi = tid + (q << 8);
            int kk = fi >> 4, c4 = fi & 15;
            const float* rowp = T + (size_t)(k0 + kk) * HDIM;
            *(float4*)&Ats[kk][c4 << 2] = *(const float4*)(rowp + m0 + (c4 << 2));
            *(float4*)&Bts[kk][c4 << 2] = *(const float4*)(rowp + n0 + (c4 << 2));
        }
        __syncthreads();
#pragma unroll
        for (int ks = 0; ks < 4; ks++) {
            int kb = ks << 3;
            uint32_t a[2][4], b[2][2];
#pragma unroll
            for (int mf = 0; mf < 2; mf++)
#pragma unroll
                for (int i = 0; i < 4; i++) {
                    int m = moff + (mf << 4) + (lane >> 2) + ((i & 1) << 3);
                    int k = kb + (lane & 3) + ((i >> 1) << 2);
                    a[mf][i] = __float_as_uint(Ats[k][m]);
                }
#pragma unroll
            for (int nf = 0; nf < 2; nf++)
#pragma unroll
                for (int i = 0; i < 2; i++) {
                    int n = noff + (nf << 3) + (lane >> 2);
                    int k = kb + (lane & 3) + (i << 2);
                    b[nf][i] = __float_as_uint(Bts[k][n]);
                }
#pragma unroll
            for (int mf = 0; mf < 2; mf++)
#pragma unroll
                for (int nf = 0; nf < 2; nf++)
                    mma_tf32(acc[mf][nf], a[mf], b[nf]);
        }
        __syncthreads();
    }
    size_t gb = (size_t)g << 20;
#pragma unroll
    for (int mf = 0; mf < 2; mf++)
#pragma unroll
        for (int nf = 0; nf < 2; nf++)
#pragma unroll
            for (int rh = 0; rh < 2; rh++) {
                int m = m0 + moff + (mf << 4) + (lane >> 2) + (rh << 3);
                int n = n0 + noff + (nf << 3) + ((lane & 3) << 1);
                float v0 = acc[mf][nf][rh << 1], v1 = acc[mf][nf][(rh << 1) + 1];
                *(__half2*)&g_Vh[gb + ((size_t)m << 10) + n] = __floats2half2_rn(v0, v1);
                if (ti != tj) {
                    g_Vh[gb + ((size_t)n << 10) + m]       = __float2half(v0);
                    g_Vh[gb + ((size_t)(n + 1) << 10) + m] = __float2half(v1);
                }
            }
}

// ---------------- persistent recurrence -------------------------------------
__global__ void __launch_bounds__(RNT, 2)
recur_kernel(const int* __restrict__ conn, float* __restrict__ tree_h) {
    extern __shared__ char sm[];
    int* s_loff = (int*)(sm + SM_LOFF);
    int* s_prow = (int*)(sm + SM_META);
    int* s_irow = s_prow + 64;
    int* s_bn   = s_prow + 128;
    uint32_t smb = (uint32_t)__cvta_generic_to_shared(sm);

    int tid = threadIdx.x, lane = tid & 31, wid = tid >> 5;
    int moff = (wid >> 1) << 4;          // wide
    int noff_w = (wid & 1) << 4;
    int g8 = lane >> 2, t2 = (lane & 3) << 1;

    // wide-path ldmatrix lane roles
    int t4 = lane >> 3, r8 = lane & 7;
    int arow = moff + ((t4 & 1) << 3) + r8;
    int a_chi = t4 >> 1;
    int brow = noff_w + ((t4 >> 1) << 3) + r8;
    int b_chi = t4 & 1;
    uint32_t aoff = (uint32_t)(arow << 7);
    int asw = arow & 7;
    uint32_t boff = (uint32_t)(brow << 7);
    int bsw = brow & 7;
    int loader_r = tid >> 3, loader_c16 = tid & 7;

    // ---- preload level_off + fixed V slice into smem ----
    for (int l = tid; l <= NNODE; l += RNT) s_loff[l] = g_level_off[l];
    int n0v = (blockIdx.x & 127) << 3;
    for (int idx = tid; idx < 24 * 128; idx += RNT) {
        int row = idx >> 7, c16 = idx & 127;
        int gg = row >> 3, cc = row & 7;
        float4 v = *(const float4*)(g_Vh + ((size_t)gg << 20)
                                    + ((size_t)(n0v + cc) << 10) + (c16 << 3));
        *(float4*)(sm + SM_VS + row * 2064 + (c16 << 4)) = v;
    }
    __syncthreads();

    int num_lv = g_num_levels;
    unsigned sync_no = 0;

    for (int lv = 1; lv < num_lv; lv++) {
        int off = s_loff[lv];
        int cnt = s_loff[lv + 1] - off;

        if (cnt > 32) {
            // ==================== WIDE PATH (3-stage) ====================
            int mtiles = (cnt + 63) >> 6;
            int total = mtiles << 5;

            for (int t = blockIdx.x; t < total; t += RNB) {
                int mt = t >> 5, nt = t & 31;
                int n0 = nt << 5;
                int mrel = mt << 6;

                if (tid < 64) {
                    int mi = off + mrel + tid;
                    int mclamp = off + cnt - 1;
                    if (mi > mclamp) mi = mclamp;
                    int m = g_meta[mi];
                    s_prow[tid] = (m & 8191) << 10;
                    int ir = (m >> 13) & 8191;
                    s_irow[tid] = ir << 10;
                    s_bn[tid]   = (ir >> 9) << 10;
                }
                __syncthreads();

                int em0 = moff + g8, em1 = moff + g8 + 8;
                int eprow0 = s_prow[em0], eprow1 = s_prow[em1];
                int ebn0 = s_bn[em0], ebn1 = s_bn[em1];
                float2 PCp[2][2];
#pragma unroll
                for (int nf = 0; nf < 2; nf++) {
                    int col = n0 + noff_w + (nf << 3) + t2;
                    PCp[0][nf] = *(const float2*)(g_tree_c + eprow0 + col);
                    PCp[1][nf] = *(const float2*)(g_tree_c + eprow1 + col);
                }

                float acc[3][2][4];
#pragma unroll
                for (int g = 0; g < 3; g++)
#pragma unroll
                    for (int nf = 0; nf < 2; nf++)
#pragma unroll
                        for (int j = 0; j < 4; j++) acc[g][nf][j] = 0.0f;

#define LOAD_STAGE(st, kc_) do {                                                       \
    int kb_ = (kc_) << 6;                                                              \
    uint32_t sbase = smb + SM_STG + (uint32_t)(st) * STAGE_BYTES;                      \
    _Pragma("unroll")                                                                  \
    for (int q = 0; q < 2; q++) {                                                      \
        int r = (q << 5) + loader_r;                                                   \
        CP_ASYNC16(sbase + (uint32_t)((r << 7) + ((loader_c16 ^ (r & 7)) << 4)),       \
                   g_hph + s_prow[r] + kb_ + (loader_c16 << 3));                       \
    }                                                                                  \
    _Pragma("unroll")                                                                  \
    for (int g = 0; g < 3; g++) {                                                      \
        int r = tid >> 3;                                                              \
        CP_ASYNC16(sbase + (uint32_t)(8192 + (g << 12) + (r << 7)                      \
                      + ((loader_c16 ^ (r & 7)) << 4)),                                \
                   g_Vh + ((size_t)g << 20) + ((size_t)(n0 + r) << 10)                 \
                        + kb_ + (loader_c16 << 3));                                    \
    }                                                                                  \
    CP_COMMIT();                                                                       \
} while (0)

                LOAD_STAGE(0, 0);
                LOAD_STAGE(1, 1);

                for (int kc = 0; kc < NKC; kc++) {
                    if (kc < NKC - 1) { CP_WAIT(1); } else { CP_WAIT(0); }
                    __syncthreads();
                    if (kc + 2 < NKC) {
                        int st = kc + 2; st -= (st >= 3) ? 3 : 0; st -= (st >= 3) ? 3 : 0;
                        // (kc+2)%3 without div for kc in 0..13
                        LOAD_STAGE((kc + 2) % 3, kc + 2);
                    }

                    uint32_t sb = smb + SM_STG + (uint32_t)(kc % 3) * STAGE_BYTES;
#pragma unroll
                    for (int ks = 0; ks < 4; ks++) {
                        int ks2 = ks << 1;
                        uint32_t a[4];
                        ldsm_x4(a, sb + aoff + (uint32_t)(((ks2 + a_chi) ^ asw) << 4));
#pragma unroll
                        for (int g = 0; g < 3; g++) {
                            uint32_t b[4];
                            ldsm_x4(b, sb + (uint32_t)(8192 + (g << 12)) + boff
                                       + (uint32_t)(((ks2 + b_chi) ^ bsw) << 4));
                            mma_f16(acc[g][0], a, b);
                            mma_f16(acc[g][1], a, b + 2);
                        }
                    }
                }

#pragma unroll
                for (int rh = 0; rh < 2; rh++) {
                    int m = moff + g8 + (rh << 3);
                    if (mrel + m < cnt) {
                        int irow = s_irow[m];
                        int bn = rh ? ebn1 : ebn0;
#pragma unroll
                        for (int nf = 0; nf < 2; nf++) {
                            int col = n0 + noff_w + (nf << 3) + t2;
                            float2 F0 = *(const float2*)(g_inp0f + bn + col);
                            float2 O0 = *(const float2*)(g_inp0o + bn + col);
                            float2 Z0 = *(const float2*)(g_inp0z + bn + col);
                            float2 PC = PCp[rh][nf];
                            float fa = acc[0][nf][rh << 1], fb = acc[0][nf][(rh << 1) + 1];
                            float oa = acc[1][nf][rh << 1], ob = acc[1][nf][(rh << 1) + 1];
                            float za = acc[2][nf][rh << 1], zb = acc[2][nf][(rh << 1) + 1];
                            float f1 = sigf(fa + F0.x), f2 = sigf(fb + F0.y);
                            float o1 = sigf(oa + O0.x), o2 = sigf(ob + O0.y);
                            float z1 = tanf_(za + Z0.x), z2 = tanf_(zb + Z0.y);
                            float c1 = PC.x * f1 + z1 * (1.0f - f1);
                            float c2 = PC.y * f2 + z2 * (1.0f - f2);
                            float h1 = o1 * tanf_(c1);
                            float h2 = o2 * tanf_(c2);
                            *(float2*)(tree_h + irow + col)   = make_float2(h1, h2);
                            *(float2*)(g_tree_c + irow + col) = make_float2(c1, c2);
                            *(__half2*)(g_hph + irow + col)   = __floats2half2_rn(h1, h2);
                        }
                    }
                }
                __syncthreads();
            }
        } else {
            // ==================== NARROW PATH (cnt <= 32, smem V) ====================
            int mt16 = (cnt + 15) >> 4;
            if ((int)blockIdx.x < (mt16 << 7)) {
                int mtile = blockIdx.x >> 7;
                int mrel = mtile << 4;
                int n0 = n0v;
                int last = cnt - 1;
                int q0 = mrel + g8;       if (q0 > last) q0 = last;
                int q1 = mrel + g8 + 8;   if (q1 > last) q1 = last;
                int m0v = g_meta[off + q0];
                int m1v = g_meta[off + q1];
                int pr0 = (m0v & 8191) << 10;
                int pr1 = (m1v & 8191) << 10;
                int colg = n0 + t2;

                // epilogue operands (warp 0 only) — issue early
                float2 F0a, F0b, O0a, O0b, Z0a, Z0b, PCa, PCb;
                int ir0 = 0, ir1 = 0;
                if (wid == 0) {
                    int irr0 = (m0v >> 13) & 8191, irr1 = (m1v >> 13) & 8191;
                    ir0 = irr0 << 10; ir1 = irr1 << 10;
                    int bna = (irr0 >> 9) << 10, bnb = (irr1 >> 9) << 10;
                    PCa = *(const float2*)(g_tree_c + pr0 + colg);
                    PCb = *(const float2*)(g_tree_c + pr1 + colg);
                    F0a = *(const float2*)(g_inp0f + bna + colg);
                    F0b = *(const float2*)(g_inp0f + bnb + colg);
                    O0a = *(const float2*)(g_inp0o + bna + colg);
                    O0b = *(const float2*)(g_inp0o + bnb + colg);
                    Z0a = *(const float2*)(g_inp0z + bna + colg);
                    Z0b = *(const float2*)(g_inp0z + bnb + colg);
                }

                float acc[3][4];
#pragma unroll
                for (int g = 0; g < 3; g++)
#pragma unroll
                    for (int q = 0; q < 4; q++) acc[g][q] = 0.0f;

                int kb0 = wid << 7;
                const __half* Ap0 = g_hph + pr0 + kb0 + t2;
                const __half* Ap1 = g_hph + pr1 + kb0 + t2;
                const __half* Vsp = (const __half*)(sm + SM_VS) + g8 * VS_ROWH + kb0 + t2;

#pragma unroll
                for (int s = 0; s < 8; s++) {
                    int ko = s << 4;
                    uint32_t a[4];
                    a[0] = *(const uint32_t*)(Ap0 + ko);
                    a[1] = *(const uint32_t*)(Ap1 + ko);
                    a[2] = *(const uint32_t*)(Ap0 + ko + 8);
                    a[3] = *(const uint32_t*)(Ap1 + ko + 8);
#pragma unroll
                    for (int g = 0; g < 3; g++) {
                        const __half* Vg = Vsp + g * (VS_ROWH << 3) + ko;
                        uint32_t b2[2];
                        b2[0] = *(const uint32_t*)(Vg);
                        b2[1] = *(const uint32_t*)(Vg + 8);
                        mma_f16(acc[g], a, b2);
                    }
                }

                // cross-warp K reduction (plain stores)
                float* red = (float*)(sm + SM_STG);
                if (wid > 0) {
                    float* rp = red + (((wid - 1) << 5) + lane) * 13;
#pragma unroll
                    for (int g = 0; g < 3; g++)
#pragma unroll
                        for (int q = 0; q < 4; q++)
                            rp[(g << 2) + q] = acc[g][q];
                }
                __syncthreads();
                if (wid == 0) {
#pragma unroll
                    for (int w = 0; w < 7; w++) {
                        float* rp = red + ((w << 5) + lane) * 13;
#pragma unroll
                        for (int g = 0; g < 3; g++)
#pragma unroll
                            for (int q = 0; q < 4; q++)
                                acc[g][q] += rp[(g << 2) + q];
                    }
#pragma unroll
                    for (int rh = 0; rh < 2; rh++) {
                        int m = g8 + (rh << 3);
                        if (mrel + m < cnt) {
                            int irow = rh ? ir1 : ir0;
                            float2 F0 = rh ? F0b : F0a;
                            float2 O0 = rh ? O0b : O0a;
                            float2 Z0 = rh ? Z0b : Z0a;
                            float2 PC = rh ? PCb : PCa;
                            float fa = acc[0][rh << 1], fb = acc[0][(rh << 1) + 1];
                            float oa = acc[1][rh << 1], ob = acc[1][(rh << 1) + 1];
                            float za = acc[2][rh << 1], zb = acc[2][(rh << 1) + 1];
                            float f1 = sigf(fa + F0.x), f2 = sigf(fb + F0.y);
                            float o1 = sigf(oa + O0.x), o2 = sigf(ob + O0.y);
                            float z1 = tanf_(za + Z0.x), z2 = tanf_(zb + Z0.y);
                            float c1 = PC.x * f1 + z1 * (1.0f - f1);
                            float c2 = PC.y * f2 + z2 * (1.0f - f2);
                            float h1 = o1 * tanf_(c1);
                            float h2 = o2 * tanf_(c2);
                            *(float2*)(tree_h + irow + colg)   = make_float2(h1, h2);
                            *(float2*)(g_tree_c + irow + colg) = make_float2(c1, c2);
                            *(__half2*)(g_hph + irow + colg)   = __floats2half2_rn(h1, h2);
                        }
                    }
                }
            }
        }

        // ---- grid barrier ----
        sync_no++;
        __syncthreads();
        if (tid == 0) {
            __threadfence();
            atomicAdd(&g_bar, 1u);
            unsigned target = sync_no * RNB;
            while (*((volatile unsigned int*)&g_bar) < target) __nanosleep(64);
            __threadfence();
        }
        __syncthreads();
    }
}

// ---------------- launch ----------------
extern "C" void kernel_launch(void* const* d_in, const int* in_sizes, int n_in,
                              void* d_out, int out_size) {
    const float* emb = (const float*)d_in[0];
    const int*   conn = (const int*)d_in[1];
    const float* Wf = (const float*)d_in[3];
    const float* bf = (const float*)d_in[4];
    const float* Wo = (const float*)d_in[5];
    const float* bo = (const float*)d_in[6];
    const float* Wz = (const float*)d_in[7];
    const float* bz = (const float*)d_in[8];
    const float* Tf = (const float*)d_in[9];
    const float* To = (const float*)d_in[10];
    const float* Tz = (const float*)d_in[11];
    float* tree_h = (float*)d_out;

    cudaFuncSetAttribute(recur_kernel, cudaFuncAttributeMaxDynamicSharedMemorySize, SMEM_TOTAL);

    setup_kernel<<<1, 512>>>(conn);                                  // launch 1
    inp0_kernel<<<128, 128>>>(emb, Wf, bf, Wo, bo, Wz, bz, tree_h);  // launch 2
    v_kernel<<<3 * NTRI, 256>>>(Tf, To, Tz);                         // launch 3
    recur_kernel<<<RNB, RNT, SMEM_TOTAL>>>(conn, tree_h);            // launch 4 = profiled
}

// round 15
// speedup vs baseline: 1.7150x; 1.7150x over previous
#include <cuda_runtime.h>
#include <cuda_fp16.h>
#include <cstdint>
#include <math.h>

#define BATCH 16
#define NNODE 512
#define IDIM  512
#define HDIM  1024

#define RNB 296          // persistent blocks, occupancy 2
#define RNT 256
#define NKC 16           // wide path: 16 k-chunks of 64 halves
#define STAGE_BYTES 20480

// dynamic SMEM layout (bytes)
#define SM_STG   0                       // 4 x 20480 = 81920
#define SM_META  81920                   // 192 ints = 768
#define SM_LOFF  82688                   // 516 ints = 2064
#define SMEM_TOTAL 84752

// ---------------- device scratch ----------------
__device__ __half g_Vh[3u * HDIM * HDIM];         // V_g fp16 [g][n][k] (symmetric)
__device__ __half g_hph[BATCH * NNODE * HDIM];    // fp16 mirror of tree_h
__device__ float  g_inp0f[BATCH * HDIM];
__device__ float  g_inp0o[BATCH * HDIM];
__device__ float  g_inp0z[BATCH * HDIM];
__device__ float  g_tree_c[BATCH * NNODE * HDIM];
__device__ int    g_meta[BATCH * NNODE];          // prow | irow<<13 (13-bit rows)
__device__ int    g_level_off[NNODE + 1];
__device__ int    g_num_levels;
__device__ unsigned int g_bar;

// ---------------- helpers ----------------
__device__ __forceinline__ void mma_tf32(float* d, const uint32_t* a, const uint32_t* b) {
    asm volatile(
        "mma.sync.aligned.m16n8k8.row.col.f32.tf32.tf32.f32 "
        "{%0,%1,%2,%3}, {%4,%5,%6,%7}, {%8,%9}, {%0,%1,%2,%3};\n"
        : "+f"(d[0]), "+f"(d[1]), "+f"(d[2]), "+f"(d[3])
        : "r"(a[0]), "r"(a[1]), "r"(a[2]), "r"(a[3]), "r"(b[0]), "r"(b[1]));
}
__device__ __forceinline__ void mma_f16(float* d, const uint32_t* a, const uint32_t* b) {
    asm volatile(
        "mma.sync.aligned.m16n8k16.row.col.f32.f16.f16.f32 "
        "{%0,%1,%2,%3}, {%4,%5,%6,%7}, {%8,%9}, {%0,%1,%2,%3};\n"
        : "+f"(d[0]), "+f"(d[1]), "+f"(d[2]), "+f"(d[3])
        : "r"(a[0]), "r"(a[1]), "r"(a[2]), "r"(a[3]), "r"(b[0]), "r"(b[1]));
}
__device__ __forceinline__ void ldsm_x4(uint32_t* r, uint32_t addr) {
    asm volatile("ldmatrix.sync.aligned.m8n8.x4.shared.b16 {%0,%1,%2,%3}, [%4];"
        : "=r"(r[0]), "=r"(r[1]), "=r"(r[2]), "=r"(r[3]) : "r"(addr));
}
#define CP_ASYNC16(dst_u32, src_ptr) \
    asm volatile("cp.async.cg.shared.global [%0], [%1], 16;" :: "r"(dst_u32), "l"(src_ptr))
#define CP_COMMIT() asm volatile("cp.async.commit_group;" ::: "memory")
#define CP_WAIT(n)  asm volatile("cp.async.wait_group %0;" :: "n"(n) : "memory")

__device__ __forceinline__ float sigf(float x) {
    return __fdividef(1.0f, 1.0f + __expf(-x));
}
__device__ __forceinline__ float tanf_(float x) {
    return 1.0f - __fdividef(2.0f, 1.0f + __expf(2.0f * x));
}

// ---------------- setup: reset + levels + counting sort + packed meta --------
__global__ void setup_kernel(const int* __restrict__ conn) {
    __shared__ unsigned short lvl[BATCH][NNODE];
    __shared__ int counts[NNODE];
    __shared__ int offs[NNODE + 1];
    __shared__ int cur[NNODE];
    int tid = threadIdx.x;
    if (tid == 0) g_bar = 0u;
    for (int l = tid; l < NNODE; l += blockDim.x) counts[l] = 0;
    __syncthreads();
    if (tid < BATCH) {
        int b = tid;
        lvl[b][0] = 0;
        for (int i = 1; i < NNODE; i++) {
            int p = conn[b * NNODE + i];
            lvl[b][i] = (unsigned short)(lvl[b][p] + 1);
        }
    }
    __syncthreads();
    for (int t = tid; t < BATCH * NNODE; t += blockDim.x) {
        int i = t & (NNODE - 1);
        if (i != 0) atomicAdd(&counts[lvl[t >> 9][i]], 1);
    }
    __syncthreads();
    if (tid == 0) {
        int acc = 0, maxl = 0;
        for (int l = 0; l < NNODE; l++) {
            offs[l] = acc;
            acc += counts[l];
            if (counts[l] > 0) maxl = l;
        }
        offs[NNODE] = acc;
        g_num_levels = maxl + 1;
    }
    __syncthreads();
    for (int l = tid; l <= NNODE; l += blockDim.x) g_level_off[l] = offs[l];
    for (int l = tid; l < NNODE; l += blockDim.x) cur[l] = offs[l];
    __syncthreads();
    for (int t = tid; t < BATCH * NNODE; t += blockDim.x) {
        int b = t >> 9, i = t & (NNODE - 1);
        if (i != 0) {
            int p = conn[b * NNODE + i];
            int pos = atomicAdd(&cur[lvl[b][i]], 1);
            g_meta[pos] = ((b << 9) + p) | (((b << 9) + i) << 13);
        }
    }
}

// ---------------- inp0 (only node 0 matters) + roots ----------------
__global__ void inp0_kernel(const float* __restrict__ emb,
                            const float* __restrict__ Wf, const float* __restrict__ bf,
                            const float* __restrict__ Wo, const float* __restrict__ bo,
                            const float* __restrict__ Wz, const float* __restrict__ bz,
                            float* __restrict__ tree_h) {
    int t = blockIdx.x * blockDim.x + threadIdx.x;
    int b = t >> 10, n = t & (HDIM - 1);
    const float* x = emb + (size_t)b * NNODE * IDIM;
    float af = bf[n], ao = bo[n], az = bz[n];
#pragma unroll 8
    for (int k = 0; k < IDIM; k++) {
        float xv = __ldg(&x[k]);
        af = fmaf(xv, Wf[k * HDIM + n], af);
        ao = fmaf(xv, Wo[k * HDIM + n], ao);
        az = fmaf(xv, Wz[k * HDIM + n], az);
    }
    g_inp0f[t] = af; g_inp0o[t] = ao; g_inp0z[t] = az;
    float f = 1.0f / (1.0f + expf(-af));
    float o = 1.0f / (1.0f + expf(-ao));
    float z = tanhf(az);
    float c = z * (1.0f - f);
    float h = o * tanhf(c);
    int row = (b * NNODE) << 10;
    tree_h[row + n] = h;
    g_hph[row + n] = __float2half(h);
    g_tree_c[row + n] = c;
}

// ---------------- V = T^T T, upper-triangular tiles + mirror ----------------
#define NTRI 136
__global__ void v_kernel(const float* __restrict__ Tf,
                         const float* __restrict__ To,
                         const float* __restrict__ Tz) {
    __shared__ float Ats[32][68];
    __shared__ float Bts[32][68];
    int bid = blockIdx.x;
    int g = bid / NTRI;
    int t = bid - g * NTRI;
    int ti = 0;
    while (t >= 16 - ti) { t -= 16 - ti; ti++; }
    int tj = ti + t;
    int m0 = ti << 6, n0 = tj << 6;
    const float* T = (g == 0) ? Tf : (g == 1) ? To : Tz;
    int tid = threadIdx.x, lane = tid & 31, wid = tid >> 5;
    int moff = (wid >> 2) << 5, noff = (wid & 3) << 4;

    float acc[2][2][4];
#pragma unroll
    for (int mf = 0; mf < 2; mf++)
#pragma unroll
        for (int nf = 0; nf < 2; nf++)
#pragma unroll
            for (int j = 0; j < 4; j++) acc[mf][nf][j] = 0.0f;

    for (int k0 = 0; k0 < HDIM; k0 += 32) {
#pragma unroll
        for (int q = 0; q < 2; q++) {
            int fi = tid + (q << 8);
            int kk = fi >> 4, c4 = fi & 15;
            const float* rowp = T + (size_t)(k0 + kk) * HDIM;
            *(float4*)&Ats[kk][c4 << 2] = *(const float4*)(rowp + m0 + (c4 << 2));
            *(float4*)&Bts[kk][c4 << 2] = *(const float4*)(rowp + n0 + (c4 << 2));
        }
        __syncthreads();
#pragma unroll
        for (int ks = 0; ks < 4; ks++) {
            int kb = ks << 3;
            uint32_t a[2][4], b[2][2];
#pragma unroll
            for (int mf = 0; mf < 2; mf++)
#pragma unroll
                for (int i = 0; i < 4; i++) {
                    int m = moff + (mf << 4) + (lane >> 2) + ((i & 1) << 3);
                    int k = kb + (lane & 3) + ((i >> 1) << 2);
                    a[mf][i] = __float_as_uint(Ats[k][m]);
                }
#pragma unroll
            for (int nf = 0; nf < 2; nf++)
#pragma unroll
                for (int i = 0; i < 2; i++) {
                    int n = noff + (nf << 3) + (lane >> 2);
                    int k = kb + (lane & 3) + (i << 2);
                    b[nf][i] = __float_as_uint(Bts[k][n]);
                }
#pragma unroll
            for (int mf = 0; mf < 2; mf++)
#pragma unroll
                for (int nf = 0; nf < 2; nf++)
                    mma_tf32(acc[mf][nf], a[mf], b[nf]);
        }
        __syncthreads();
    }
    size_t gb = (size_t)g << 20;
#pragma unroll
    for (int mf = 0; mf < 2; mf++)
#pragma unroll
        for (int nf = 0; nf < 2; nf++)
#pragma unroll
            for (int rh = 0; rh < 2; rh++) {
                int m = m0 + moff + (mf << 4) + (lane >> 2) + (rh << 3);
                int n = n0 + noff + (nf << 3) + ((lane & 3) << 1);
                float v0 = acc[mf][nf][rh << 1], v1 = acc[mf][nf][(rh << 1) + 1];
                *(__half2*)&g_Vh[gb + ((size_t)m << 10) + n] = __floats2half2_rn(v0, v1);
                if (ti != tj) {
                    g_Vh[gb + ((size_t)n << 10) + m]       = __float2half(v0);
                    g_Vh[gb + ((size_t)(n + 1) << 10) + m] = __float2half(v1);
                }
            }
}

// ---------------- persistent recurrence -------------------------------------
// Wide path (cnt>32): R10/R13 M=64 x N=32 smem/ldmatrix tiles, 4-stage pipeline.
// Narrow path (cnt<=32): one-shot m16 x n8 x 3g tiles, direct-LDG fragments,
// K split over 8 warps, register meta, smem-store reduction, warp-0 epilogue.
__global__ void __launch_bounds__(RNT, 2)
recur_kernel(const int* __restrict__ conn, float* __restrict__ tree_h) {
    extern __shared__ char sm[];
    int* s_prow = (int*)(sm + SM_META);
    int* s_irow = s_prow + 64;
    int* s_bn   = s_prow + 128;
    int* s_loff = (int*)(sm + SM_LOFF);
    uint32_t smb = (uint32_t)__cvta_generic_to_shared(sm);

    int tid = threadIdx.x, lane = tid & 31, wid = tid >> 5;
    int moff = (wid >> 1) << 4;          // wide: 0,16,32,48
    int noff_w = (wid & 1) << 4;         // wide: 0,16
    int g8 = lane >> 2, t2 = (lane & 3) << 1;

    // wide-path ldmatrix lane roles
    int t4 = lane >> 3, r8 = lane & 7;
    int arow = moff + ((t4 & 1) << 3) + r8;
    int a_chi = t4 >> 1;
    int brow = noff_w + ((t4 >> 1) << 3) + r8;
    int b_chi = t4 & 1;
    uint32_t aoff = (uint32_t)(arow << 7);
    int asw = arow & 7;
    uint32_t boff = (uint32_t)(brow << 7);
    int bsw = brow & 7;
    int loader_r = tid >> 3, loader_c16 = tid & 7;

    for (int l = tid; l <= NNODE; l += RNT) s_loff[l] = g_level_off[l];
    __syncthreads();

    int num_lv = g_num_levels;
    unsigned sync_no = 0;

    for (int lv = 1; lv < num_lv; lv++) {
        int off = s_loff[lv];
        int cnt = s_loff[lv + 1] - off;

        if (cnt > 32) {
            // ==================== WIDE PATH ====================
            int mtiles = (cnt + 63) >> 6;
            int total = mtiles << 5;

            for (int t = blockIdx.x; t < total; t += RNB) {
                int mt = t >> 5, nt = t & 31;
                int n0 = nt << 5;
                int mrel = mt << 6;

                if (tid < 64) {
                    int mi = off + mrel + tid;
                    int mclamp = off + cnt - 1;
                    if (mi > mclamp) mi = mclamp;
                    int m = g_meta[mi];
                    s_prow[tid] = (m & 8191) << 10;
                    int ir = (m >> 13) & 8191;
                    s_irow[tid] = ir << 10;
                    s_bn[tid]   = (ir >> 9) << 10;
                }
                __syncthreads();

                // epilogue prefetch
                int em0 = moff + g8, em1 = moff + g8 + 8;
                int eprow0 = s_prow[em0], eprow1 = s_prow[em1];
                int ebn0 = s_bn[em0], ebn1 = s_bn[em1];
                float2 PCp[2][2];
#pragma unroll
                for (int nf = 0; nf < 2; nf++) {
                    int col = n0 + noff_w + (nf << 3) + t2;
                    PCp[0][nf] = *(const float2*)(g_tree_c + eprow0 + col);
                    PCp[1][nf] = *(const float2*)(g_tree_c + eprow1 + col);
                }

                float acc[3][2][4];
#pragma unroll
                for (int g = 0; g < 3; g++)
#pragma unroll
                    for (int nf = 0; nf < 2; nf++)
#pragma unroll
                        for (int j = 0; j < 4; j++) acc[g][nf][j] = 0.0f;

#define LOAD_STAGE(st, kc_) do {                                                       \
    int kb_ = (kc_) << 6;                                                              \
    uint32_t sbase = smb + SM_STG + (uint32_t)(st) * STAGE_BYTES;                      \
    _Pragma("unroll")                                                                  \
    for (int q = 0; q < 2; q++) {                                                      \
        int r = (q << 5) + loader_r;                                                   \
        CP_ASYNC16(sbase + (uint32_t)((r << 7) + ((loader_c16 ^ (r & 7)) << 4)),       \
                   g_hph + s_prow[r] + kb_ + (loader_c16 << 3));                       \
    }                                                                                  \
    _Pragma("unroll")                                                                  \
    for (int g = 0; g < 3; g++) {                                                      \
        int r = tid >> 3;                                                              \
        CP_ASYNC16(sbase + (uint32_t)(8192 + (g << 12) + (r << 7)                      \
                      + ((loader_c16 ^ (r & 7)) << 4)),                                \
                   g_Vh + ((size_t)g << 20) + ((size_t)(n0 + r) << 10)                 \
                        + kb_ + (loader_c16 << 3));                                    \
    }                                                                                  \
    CP_COMMIT();                                                                       \
} while (0)

                LOAD_STAGE(0, 0);
                LOAD_STAGE(1, 1);
                LOAD_STAGE(2, 2);

                for (int kc = 0; kc < NKC; kc++) {
                    int rem = NKC - 1 - kc;
                    if (rem >= 2) { CP_WAIT(2); }
                    else if (rem == 1) { CP_WAIT(1); }
                    else { CP_WAIT(0); }
                    __syncthreads();
                    if (kc + 3 < NKC) LOAD_STAGE((kc + 3) & 3, kc + 3);

                    uint32_t sb = smb + SM_STG + (uint32_t)(kc & 3) * STAGE_BYTES;
#pragma unroll
                    for (int ks = 0; ks < 4; ks++) {
                        int ks2 = ks << 1;
                        uint32_t a[4];
                        ldsm_x4(a, sb + aoff + (uint32_t)(((ks2 + a_chi) ^ asw) << 4));
#pragma unroll
                        for (int g = 0; g < 3; g++) {
                            uint32_t b[4];
                            ldsm_x4(b, sb + (uint32_t)(8192 + (g << 12)) + boff
                                       + (uint32_t)(((ks2 + b_chi) ^ bsw) << 4));
                            mma_f16(acc[g][0], a, b);
                            mma_f16(acc[g][1], a, b + 2);
                        }
                    }
                }

                // fused LSTM epilogue
#pragma unroll
                for (int rh = 0; rh < 2; rh++) {
                    int m = moff + g8 + (rh << 3);
                    if (mrel + m < cnt) {
                        int irow = s_irow[m];
                        int bn = rh ? ebn1 : ebn0;
#pragma unroll
                        for (int nf = 0; nf < 2; nf++) {
                            int col = n0 + noff_w + (nf << 3) + t2;
                            float2 F0 = *(const float2*)(g_inp0f + bn + col);
                            float2 O0 = *(const float2*)(g_inp0o + bn + col);
                            float2 Z0 = *(const float2*)(g_inp0z + bn + col);
                            float2 PC = PCp[rh][nf];
                            float fa = acc[0][nf][rh << 1], fb = acc[0][nf][(rh << 1) + 1];
                            float oa = acc[1][nf][rh << 1], ob = acc[1][nf][(rh << 1) + 1];
                            float za = acc[2][nf][rh << 1], zb = acc[2][nf][(rh << 1) + 1];
                            float f1 = sigf(fa + F0.x), f2 = sigf(fb + F0.y);
                            float o1 = sigf(oa + O0.x), o2 = sigf(ob + O0.y);
                            float z1 = tanf_(za + Z0.x), z2 = tanf_(zb + Z0.y);
                            float c1 = PC.x * f1 + z1 * (1.0f - f1);
                            float c2 = PC.y * f2 + z2 * (1.0f - f2);
                            float h1 = o1 * tanf_(c1);
                            float h2 = o2 * tanf_(c2);
                            *(float2*)(tree_h + irow + col)   = make_float2(h1, h2);
                            *(float2*)(g_tree_c + irow + col) = make_float2(c1, c2);
                            *(__half2*)(g_hph + irow + col)   = __floats2half2_rn(h1, h2);
                        }
                    }
                }
                __syncthreads();
            }
        } else {
            // ==================== NARROW PATH (cnt <= 32, register meta) ========
            int mt16 = (cnt + 15) >> 4;
            if ((int)blockIdx.x < (mt16 << 7)) {
                int mtile = blockIdx.x >> 7, nt = blockIdx.x & 127;
                int n0 = nt << 3;
                int mrel = mtile << 4;
                int last = cnt - 1;
                int q0 = mrel + g8;       if (q0 > last) q0 = last;
                int q1 = mrel + g8 + 8;   if (q1 > last) q1 = last;
                int m0v = g_meta[off + q0];
                int m1v = g_meta[off + q1];
                int pr0 = (m0v & 8191) << 10;
                int pr1 = (m1v & 8191) << 10;
                int colg = n0 + t2;

                // epilogue operands (warp 0 only) — issue early
                float2 F0a, F0b, O0a, O0b, Z0a, Z0b, PCa, PCb;
                int ir0 = 0, ir1 = 0;
                if (wid == 0) {
                    int irr0 = (m0v >> 13) & 8191, irr1 = (m1v >> 13) & 8191;
                    ir0 = irr0 << 10; ir1 = irr1 << 10;
                    int bna = (irr0 >> 9) << 10, bnb = (irr1 >> 9) << 10;
                    PCa = *(const float2*)(g_tree_c + pr0 + colg);
                    PCb = *(const float2*)(g_tree_c + pr1 + colg);
                    F0a = *(const float2*)(g_inp0f + bna + colg);
                    F0b = *(const float2*)(g_inp0f + bnb + colg);
                    O0a = *(const float2*)(g_inp0o + bna + colg);
                    O0b = *(const float2*)(g_inp0o + bnb + colg);
                    Z0a = *(const float2*)(g_inp0z + bna + colg);
                    Z0b = *(const float2*)(g_inp0z + bnb + colg);
                }

                float acc[3][4];
#pragma unroll
                for (int g = 0; g < 3; g++)
#pragma unroll
                    for (int q = 0; q < 4; q++) acc[g][q] = 0.0f;

                int kb0 = wid << 7;              // warp K-segment (128)
                const __half* Ap0 = g_hph + pr0 + kb0 + t2;
                const __half* Ap1 = g_hph + pr1 + kb0 + t2;
                const __half* Vp  = g_Vh + ((size_t)(n0 + g8) << 10) + kb0 + t2;

#pragma unroll 4
                for (int s = 0; s < 8; s++) {
                    int ko = s << 4;
                    uint32_t a[4];
                    a[0] = *(const uint32_t*)(Ap0 + ko);
                    a[1] = *(const uint32_t*)(Ap1 + ko);
                    a[2] = *(const uint32_t*)(Ap0 + ko + 8);
                    a[3] = *(const uint32_t*)(Ap1 + ko + 8);
#pragma unroll
                    for (int g = 0; g < 3; g++) {
                        const __half* Vg = Vp + ((size_t)g << 20) + ko;
                        uint32_t b2[2];
                        b2[0] = *(const uint32_t*)(Vg);
                        b2[1] = *(const uint32_t*)(Vg + 8);
                        mma_f16(acc[g], a, b2);
                    }
                }

                // cross-warp K reduction: warps 1..7 store, warp 0 sums
                float* red = (float*)(sm + SM_STG);
                if (wid > 0) {
                    float* rp = red + (((wid - 1) << 5) + lane) * 13;
#pragma unroll
                    for (int g = 0; g < 3; g++)
#pragma unroll
                        for (int q = 0; q < 4; q++)
                            rp[(g << 2) + q] = acc[g][q];
                }
                __syncthreads();
                if (wid == 0) {
#pragma unroll
                    for (int w = 0; w < 7; w++) {
                        float* rp = red + ((w << 5) + lane) * 13;
#pragma unroll
                        for (int g = 0; g < 3; g++)
#pragma unroll
                            for (int q = 0; q < 4; q++)
                                acc[g][q] += rp[(g << 2) + q];
                    }
                    // fused LSTM epilogue
#pragma unroll
                    for (int rh = 0; rh < 2; rh++) {
                        int m = g8 + (rh << 3);
                        if (mrel + m < cnt) {
                            int irow = rh ? ir1 : ir0;
                            float2 F0 = rh ? F0b : F0a;
                            float2 O0 = rh ? O0b : O0a;
                            float2 Z0 = rh ? Z0b : Z0a;
                            float2 PC = rh ? PCb : PCa;
                            float fa = acc[0][rh << 1], fb = acc[0][(rh << 1) + 1];
                            float oa = acc[1][rh << 1], ob = acc[1][(rh << 1) + 1];
                            float za = acc[2][rh << 1], zb = acc[2][(rh << 1) + 1];
                            float f1 = sigf(fa + F0.x), f2 = sigf(fb + F0.y);
                            float o1 = sigf(oa + O0.x), o2 = sigf(ob + O0.y);
                            float z1 = tanf_(za + Z0.x), z2 = tanf_(zb + Z0.y);
                            float c1 = PC.x * f1 + z1 * (1.0f - f1);
                            float c2 = PC.y * f2 + z2 * (1.0f - f2);
                            float h1 = o1 * tanf_(c1);
                            float h2 = o2 * tanf_(c2);
                            *(float2*)(tree_h + irow + colg)   = make_float2(h1, h2);
                            *(float2*)(g_tree_c + irow + colg) = make_float2(c1, c2);
                            *(__half2*)(g_hph + irow + colg)   = __floats2half2_rn(h1, h2);
                        }
                    }
                }
                __syncthreads();
            }
        }

        // ---- grid barrier ----
        sync_no++;
        __syncthreads();
        if (tid == 0) {
            __threadfence();
            atomicAdd(&g_bar, 1u);
            unsigned target = sync_no * RNB;
            while (*((volatile unsigned int*)&g_bar) < target) __nanosleep(64);
            __threadfence();
        }
        __syncthreads();
    }
}

// ---------------- launch ----------------
extern "C" void kernel_launch(void* const* d_in, const int* in_sizes, int n_in,
                              void* d_out, int out_size) {
    const float* emb = (const float*)d_in[0];
    const int*   conn = (const int*)d_in[1];
    const float* Wf = (const float*)d_in[3];
    const float* bf = (const float*)d_in[4];
    const float* Wo = (const float*)d_in[5];
    const float* bo = (const float*)d_in[6];
    const float* Wz = (const float*)d_in[7];
    const float* bz = (const float*)d_in[8];
    const float* Tf = (const float*)d_in[9];
    const float* To = (const float*)d_in[10];
    const float* Tz = (const float*)d_in[11];
    float* tree_h = (float*)d_out;

    cudaFuncSetAttribute(recur_kernel, cudaFuncAttributeMaxDynamicSharedMemorySize, SMEM_TOTAL);

    setup_kernel<<<1, 512>>>(conn);                                  // launch 1
    inp0_kernel<<<128, 128>>>(emb, Wf, bf, Wo, bo, Wz, bz, tree_h);  // launch 2
    v_kernel<<<3 * NTRI, 256>>>(Tf, To, Tz);                         // launch 3
    recur_kernel<<<RNB, RNT, SMEM_TOTAL>>>(conn, tree_h);            // launch 4 = profiled
}